// round 12
// baseline (speedup 1.0000x reference)
#include <cuda_runtime.h>
#include <cuda_bf16.h>
#include <cstdint>

// Problem constants (match reference)
#define N_ATOMS 200000
#define N_PAIRS 8000000
#define N_CH 4

#define NUM_SMS 148
#define CTAS_PER_SM 8
#define THREADS 256

__device__ __forceinline__ void red4(float4* ptr, float4 v, float wt)
{
    asm volatile("red.global.add.v4.f32 [%0], {%1, %2, %3, %4};"
                 :: "l"(ptr), "f"(v.x * wt), "f"(v.y * wt),
                    "f"(v.z * wt), "f"(v.w * wt) : "memory");
}

// L1-no-allocate 16B gather (random gathers over a 3.2MB L2-resident table:
// ~0 L1 reuse, keep the L1tex pipeline light).
__device__ __forceinline__ float4 ldcg4(const float4* p)
{
    float4 r;
    asm volatile("ld.global.cg.v4.f32 {%0, %1, %2, %3}, [%4];"
                 : "=f"(r.x), "=f"(r.y), "=f"(r.z), "=f"(r.w) : "l"(p));
    return r;
}

// Persistent grid-stride kernel: exactly one wave of 148x8 CTAs, each thread
// loops over ~26 pairs. Next iteration's index/distance loads are prefetched
// so the serial chain per iteration is only gather->RED (idx latency hidden
// behind the previous iteration's memory ops).
__global__ void __launch_bounds__(THREADS) pair_scatter_kernel(
    const float4* __restrict__ charges,     // N_ATOMS
    const int2*   __restrict__ nbr_idx,     // N_PAIRS
    const float*  __restrict__ nbr_dist,    // N_PAIRS
    float4*       __restrict__ potential)   // N_ATOMS
{
    const int stride = gridDim.x * THREADS;
    int p = blockIdx.x * THREADS + threadIdx.x;
    if (p >= N_PAIRS) return;

    // Prologue load
    int2  ij = __ldcs(&nbr_idx[p]);
    float d  = __ldcs(&nbr_dist[p]);

    while (true) {
        const int pn = p + stride;
        const bool more = pn < N_PAIRS;

        // Prefetch next iteration's coalesced streams before touching this
        // iteration's random gathers.
        int2  ij_n;
        float d_n;
        if (more) {
            ij_n = __ldcs(&nbr_idx[pn]);
            d_n  = __ldcs(&nbr_dist[pn]);
        }

        const float w  = __fdividef(0.5f, d);
        const float4 ci = ldcg4(&charges[ij.x]);
        const float4 cj = ldcg4(&charges[ij.y]);

        red4(potential + ij.x, cj, w);
        red4(potential + ij.y, ci, w);

        if (!more) break;
        p  = pn;
        ij = ij_n;
        d  = d_n;
    }
}

extern "C" void kernel_launch(void* const* d_in, const int* in_sizes, int n_in,
                              void* d_out, int out_size)
{
    const float4* charges  = (const float4*)d_in[0];  // N_ATOMS*4 f32
    const int2*   nbr_idx  = (const int2*)d_in[1];    // N_PAIRS*2 i32
    const float*  nbr_dist = (const float*)d_in[2];   // N_PAIRS f32
    float4*       out      = (float4*)d_out;          // N_ATOMS*4 f32

    // Output is accumulated into; zero it (memset node is graph-capturable).
    cudaMemsetAsync(d_out, 0, (size_t)out_size * sizeof(float));

    const int blocks = NUM_SMS * CTAS_PER_SM;   // 1184 CTAs = exactly one wave
    pair_scatter_kernel<<<blocks, THREADS>>>(charges, nbr_idx, nbr_dist, out);
}

// round 13
// speedup vs baseline: 1.1017x; 1.1017x over previous
#include <cuda_runtime.h>
#include <cuda_bf16.h>
#include <cstdint>

// Problem constants (match reference)
#define N_ATOMS 200000
#define N_PAIRS 8000000
#define N_CH 4

__device__ __forceinline__ void red4(float4* ptr, float4 v, float wt)
{
    asm volatile("red.global.add.v4.f32 [%0], {%1, %2, %3, %4};"
                 :: "l"(ptr), "f"(v.x * wt), "f"(v.y * wt),
                    "f"(v.z * wt), "f"(v.w * wt) : "memory");
}

// One pair per thread — best-measured configuration across 6 variants:
// max warps (19 regs), minimal front-batched LDG count per CTA (lowest
// cross-CTA L1tex-queue spread), hardware CTA scheduler instead of a
// software loop. Per pair: 2 coalesced stream loads, 2 random 16B gathers
// (L2-resident charges table), 2 vectorized fire-and-forget L2 reductions.
__global__ void __launch_bounds__(256) pair_scatter_kernel(
    const float4* __restrict__ charges,     // N_ATOMS
    const int2*   __restrict__ nbr_idx,     // N_PAIRS
    const float*  __restrict__ nbr_dist,    // N_PAIRS
    float4*       __restrict__ potential)   // N_ATOMS
{
    int p = blockIdx.x * blockDim.x + threadIdx.x;
    if (p >= N_PAIRS) return;

    int2  ij = nbr_idx[p];
    float d  = nbr_dist[p];
    float w  = __fdividef(0.5f, d);   // MUFU.RCP path; |err| ~2^-22 << 1e-3 budget

    float4 ci = __ldg(&charges[ij.x]);
    float4 cj = __ldg(&charges[ij.y]);

    red4(potential + ij.x, cj, w);
    red4(potential + ij.y, ci, w);
}

extern "C" void kernel_launch(void* const* d_in, const int* in_sizes, int n_in,
                              void* d_out, int out_size)
{
    const float4* charges  = (const float4*)d_in[0];  // N_ATOMS*4 f32
    const int2*   nbr_idx  = (const int2*)d_in[1];    // N_PAIRS*2 i32
    const float*  nbr_dist = (const float*)d_in[2];   // N_PAIRS f32
    float4*       out      = (float4*)d_out;          // N_ATOMS*4 f32

    // Output is accumulated into; zero it (memset node is graph-capturable).
    cudaMemsetAsync(d_out, 0, (size_t)out_size * sizeof(float));

    const int threads = 256;
    const int blocks  = (N_PAIRS + threads - 1) / threads;
    pair_scatter_kernel<<<blocks, threads>>>(charges, nbr_idx, nbr_dist, out);
}

// round 17
// speedup vs baseline: 1.1031x; 1.0013x over previous
#include <cuda_runtime.h>
#include <cuda_bf16.h>
#include <cstdint>

// Problem constants (match reference)
#define N_ATOMS 200000
#define N_PAIRS 8000000
#define N_CH 4
#define THREADS 128   // 8,000,000 % 128 == 0 -> no bounds check needed

__device__ __forceinline__ void red4(float4* ptr, float4 v, float wt)
{
    asm volatile("red.global.add.v4.f32 [%0], {%1, %2, %3, %4};"
                 :: "l"(ptr), "f"(v.x * wt), "f"(v.y * wt),
                    "f"(v.z * wt), "f"(v.w * wt) : "memory");
}

// One pair per thread — confirmed-best formulation (roofline: 32M random
// L1tex/LTS requests, ~114us floor; we run at ~95% of it). Per pair:
// 2 coalesced stream loads, 2 random 16B gathers (charges table is
// L2-resident), 2 vectorized fire-and-forget L2 reductions.
// 128-thread CTAs: finest scheduling granularity, halves the per-CTA
// front-batched LDG burst into the L1tex queue.
__global__ void __launch_bounds__(THREADS) pair_scatter_kernel(
    const float4* __restrict__ charges,     // N_ATOMS
    const int2*   __restrict__ nbr_idx,     // N_PAIRS
    const float*  __restrict__ nbr_dist,    // N_PAIRS
    float4*       __restrict__ potential)   // N_ATOMS
{
    int p = blockIdx.x * THREADS + threadIdx.x;   // grid exactly covers N_PAIRS

    int2  ij = nbr_idx[p];
    float d  = nbr_dist[p];
    float w  = __fdividef(0.5f, d);   // MUFU.RCP; |err| ~2^-22 << 1e-3 budget

    float4 ci = __ldg(&charges[ij.x]);
    float4 cj = __ldg(&charges[ij.y]);

    red4(potential + ij.x, cj, w);
    red4(potential + ij.y, ci, w);
}

extern "C" void kernel_launch(void* const* d_in, const int* in_sizes, int n_in,
                              void* d_out, int out_size)
{
    const float4* charges  = (const float4*)d_in[0];  // N_ATOMS*4 f32
    const int2*   nbr_idx  = (const int2*)d_in[1];    // N_PAIRS*2 i32
    const float*  nbr_dist = (const float*)d_in[2];   // N_PAIRS f32
    float4*       out      = (float4*)d_out;          // N_ATOMS*4 f32

    // Output is accumulated into; zero it (memset node is graph-capturable).
    cudaMemsetAsync(d_out, 0, (size_t)out_size * sizeof(float));

    pair_scatter_kernel<<<N_PAIRS / THREADS, THREADS>>>(charges, nbr_idx,
                                                        nbr_dist, out);
}